// round 6
// baseline (speedup 1.0000x reference)
#include <cuda_runtime.h>
#include <cuda_bf16.h>

// CenterLoss collapses: the label mask keeps only distmat[b, labels[b]]; all
// other B*(C-1) entries are 0 -> clamped to CLAMP_MIN.
// loss = (sum_b clamp(||x_b - c_{lbl_b}||^2, MIN, MAX)) / B + (C-1)*CLAMP_MIN.
//
// Labels are INT32 (established R2..R5: int64 read gives rel_err 9.26e-2,
// int32 gives 1.19e-7). Single fused kernel: R3 proved the last-block
// reduction protocol numerically matches the two-kernel version; R5 showed
// the separate reduce launch costs 4.6us of pure overhead.

#define BATCH 4096
#define NUM_CLASSES 100000
#define FEAT_DIM 64
#define CLAMP_MIN_F 1e-12f
#define CLAMP_MAX_F 1e12f

#define BLOCK_THREADS 256
#define WARPS_PER_BLOCK (BLOCK_THREADS / 32)        // 8 rows per block
#define NUM_BLOCKS (BATCH / WARPS_PER_BLOCK)        // 512

__device__ float        g_partials[NUM_BLOCKS];
__device__ unsigned int g_arrive_count = 0;         // last block resets -> replay-safe

__global__ void __launch_bounds__(BLOCK_THREADS)
center_loss_fused(const float* __restrict__ x,
                  const float* __restrict__ centers,
                  const int* __restrict__ labels,
                  float* __restrict__ out) {
    const int warp_in_block = threadIdx.x >> 5;
    const int lane = threadIdx.x & 31;
    const int row = blockIdx.x * WARPS_PER_BLOCK + warp_in_block;   // < BATCH

    int lbl = labels[row];
    // Crash guard (free): a bad label can only give a wrong value, never a fault.
    if (lbl < 0) lbl = 0;
    if (lbl >= NUM_CLASSES) lbl = NUM_CLASSES - 1;

    // 64 floats per row = 32 lanes x float2; fully coalesced 256B rows.
    const float2 xv = reinterpret_cast<const float2*>(x + (size_t)row * FEAT_DIM)[lane];
    const float2 cv = reinterpret_cast<const float2*>(centers + (size_t)lbl * FEAT_DIM)[lane];

    const float d0 = xv.x - cv.x;
    const float d1 = xv.y - cv.y;
    float sum = d0 * d0 + d1 * d1;

    #pragma unroll
    for (int o = 16; o > 0; o >>= 1)
        sum += __shfl_xor_sync(0xffffffffu, sum, o);

    __shared__ float ws[WARPS_PER_BLOCK];
    if (lane == 0)
        ws[warp_in_block] = fminf(fmaxf(sum, CLAMP_MIN_F), CLAMP_MAX_F);  // clip-then-sum
    __syncthreads();

    // Block partial -> slot; arrive. (threadFenceReduction pattern)
    __shared__ bool s_is_last;
    if (threadIdx.x == 0) {
        float v = 0.0f;
        #pragma unroll
        for (int w = 0; w < WARPS_PER_BLOCK; w++) v += ws[w];
        g_partials[blockIdx.x] = v;
        __threadfence();                                  // release partial
        unsigned int t = atomicAdd(&g_arrive_count, 1u);
        s_is_last = (t == NUM_BLOCKS - 1);
    }
    __syncthreads();

    // Last-arriving block: all 511 other partials are globally visible
    // (each was released by __threadfence before its atomicAdd).
    if (s_is_last) {
        __threadfence();                                  // acquire side

        float v = g_partials[threadIdx.x] + g_partials[threadIdx.x + BLOCK_THREADS];

        #pragma unroll
        for (int o = 16; o > 0; o >>= 1)
            v += __shfl_xor_sync(0xffffffffu, v, o);

        __shared__ float fs[WARPS_PER_BLOCK];
        if (lane == 0) fs[threadIdx.x >> 5] = v;
        __syncthreads();

        if (threadIdx.x == 0) {
            float w = 0.0f;
            #pragma unroll
            for (int i = 0; i < WARPS_PER_BLOCK; i++) w += fs[i];
            // (C-1) masked zeros per row -> CLAMP_MIN each; /B leaves (C-1)*MIN.
            const float mask_term = (float)(NUM_CLASSES - 1) * CLAMP_MIN_F;
            out[0] = w / (float)BATCH + mask_term;
            __threadfence();
            g_arrive_count = 0;                           // reset for next replay
        }
    }
}

extern "C" void kernel_launch(void* const* d_in, const int* in_sizes, int n_in,
                              void* d_out, int out_size) {
    const float* x       = (const float*)d_in[0];
    const float* centers = (const float*)d_in[1];
    const int*   labels  = (const int*)d_in[2];
    float* out = (float*)d_out;

    center_loss_fused<<<NUM_BLOCKS, BLOCK_THREADS>>>(x, centers, labels, out);
}

// round 7
// speedup vs baseline: 1.0964x; 1.0964x over previous
#include <cuda_runtime.h>
#include <cuda_bf16.h>

// CenterLoss collapses: the label mask keeps only distmat[b, labels[b]]; all
// other B*(C-1) entries are 0 -> clamped to CLAMP_MIN.
// loss = (sum_b clamp(||x_b - c_{lbl_b}||^2, MIN, MAX)) / B + (C-1)*CLAMP_MIN.
// Labels are INT32 (established R2..R5).
//
// R6 lesson: __threadfence() (gpu scope) emits CCTL.IVALL (L1 flush) + MEMBAR
// in every block leader -> ~5us of sync overhead. Here the handshake is a
// single atom.add.acq_rel (no membar, no L1 flush); partials move through L2
// via st.cg/ld.cg so L1 incoherence is irrelevant.

#define BATCH 4096
#define NUM_CLASSES 100000
#define FEAT_DIM 64
#define CLAMP_MIN_F 1e-12f
#define CLAMP_MAX_F 1e12f

#define BLOCK_THREADS 256
#define WARPS_PER_BLOCK 8
#define ROWS_PER_WARP 2
#define ROWS_PER_BLOCK (WARPS_PER_BLOCK * ROWS_PER_WARP)   // 16
#define NUM_BLOCKS (BATCH / ROWS_PER_BLOCK)                // 256

__device__ float        g_partials[NUM_BLOCKS];
__device__ unsigned int g_arrive_count = 0;   // last block resets -> replay-safe

__global__ void __launch_bounds__(BLOCK_THREADS)
center_loss_fused(const float* __restrict__ x,
                  const float* __restrict__ centers,
                  const int* __restrict__ labels,
                  float* __restrict__ out) {
    const int warp = threadIdx.x >> 5;
    const int lane = threadIdx.x & 31;
    const int row0 = blockIdx.x * ROWS_PER_BLOCK + warp * ROWS_PER_WARP;
    const int row1 = row0 + 1;

    int l0 = labels[row0];
    int l1 = labels[row1];
    // Crash guard (free): bad label -> wrong value, never a fault.
    l0 = (l0 < 0) ? 0 : (l0 >= NUM_CLASSES ? NUM_CLASSES - 1 : l0);
    l1 = (l1 < 0) ? 0 : (l1 >= NUM_CLASSES ? NUM_CLASSES - 1 : l1);

    // 4 independent 8B loads per lane -> MLP hides the label->center chain.
    const float2 xv0 = reinterpret_cast<const float2*>(x + (size_t)row0 * FEAT_DIM)[lane];
    const float2 xv1 = reinterpret_cast<const float2*>(x + (size_t)row1 * FEAT_DIM)[lane];
    const float2 cv0 = reinterpret_cast<const float2*>(centers + (size_t)l0 * FEAT_DIM)[lane];
    const float2 cv1 = reinterpret_cast<const float2*>(centers + (size_t)l1 * FEAT_DIM)[lane];

    const float e0 = xv0.x - cv0.x, e1 = xv0.y - cv0.y;
    const float f0 = xv1.x - cv1.x, f1 = xv1.y - cv1.y;
    float a0 = e0 * e0 + e1 * e1;
    float a1 = f0 * f0 + f1 * f1;

    #pragma unroll
    for (int o = 16; o > 0; o >>= 1) {
        a0 += __shfl_xor_sync(0xffffffffu, a0, o);
        a1 += __shfl_xor_sync(0xffffffffu, a1, o);
    }

    __shared__ float ws[WARPS_PER_BLOCK];
    if (lane == 0) {
        // clamp per ROW (clip-then-sum, faithful to reference)
        const float c0 = fminf(fmaxf(a0, CLAMP_MIN_F), CLAMP_MAX_F);
        const float c1 = fminf(fmaxf(a1, CLAMP_MIN_F), CLAMP_MAX_F);
        ws[warp] = c0 + c1;
    }
    __syncthreads();

    __shared__ bool s_is_last;
    if (threadIdx.x == 0) {
        float v = 0.0f;
        #pragma unroll
        for (int w = 0; w < WARPS_PER_BLOCK; w++) v += ws[w];
        __stcg(&g_partials[blockIdx.x], v);               // publish via L2
        unsigned int t;
        asm volatile("atom.add.acq_rel.gpu.global.u32 %0, [%1], 1;"
                     : "=r"(t) : "l"(&g_arrive_count) : "memory");
        s_is_last = (t == NUM_BLOCKS - 1);
    }
    __syncthreads();

    // Last-arriving block: every other partial was released (st.cg + release
    // ordering of its atom) before its counter bump; read via L2.
    if (s_is_last) {
        float v = __ldcg(&g_partials[threadIdx.x]);       // 256 slots, 256 threads

        #pragma unroll
        for (int o = 16; o > 0; o >>= 1)
            v += __shfl_xor_sync(0xffffffffu, v, o);

        __shared__ float fs[WARPS_PER_BLOCK];
        if (lane == 0) fs[warp] = v;
        __syncthreads();

        if (threadIdx.x == 0) {
            float w = 0.0f;
            #pragma unroll
            for (int i = 0; i < WARPS_PER_BLOCK; i++) w += fs[i];
            // (C-1) masked zeros per row -> CLAMP_MIN each; /B leaves (C-1)*MIN.
            const float mask_term = (float)(NUM_CLASSES - 1) * CLAMP_MIN_F;
            out[0] = w / (float)BATCH + mask_term;
            g_arrive_count = 0;   // visible to next replay via kernel boundary
        }
    }
}

extern "C" void kernel_launch(void* const* d_in, const int* in_sizes, int n_in,
                              void* d_out, int out_size) {
    const float* x       = (const float*)d_in[0];
    const float* centers = (const float*)d_in[1];
    const int*   labels  = (const int*)d_in[2];
    float* out = (float*)d_out;

    center_loss_fused<<<NUM_BLOCKS, BLOCK_THREADS>>>(x, centers, labels, out);
}

// round 8
// speedup vs baseline: 1.2757x; 1.1636x over previous
#include <cuda_runtime.h>
#include <cuda_bf16.h>

// CenterLoss collapses: the label mask keeps only distmat[b, labels[b]]; all
// other B*(C-1) entries are 0 -> clamped to CLAMP_MIN.
// loss = (sum_b clamp(||x_b - c_{lbl_b}||^2, MIN, MAX)) / B + (C-1)*CLAMP_MIN.
// Labels are INT32 (established R2..R5).
//
// R6/R7 lesson: in-kernel grid sync (fence or acq_rel atomic + tail) costs
// more than a second launch; R5's two-kernel 7.14us still beat both fusions.
// R8: keep two kernels but OVERLAP them with PDL (programmatic dependent
// launch). Kernel 2 launches while kernel 1 runs and blocks in
// cudaGridDependencySynchronize(); no atomics or fences anywhere.

#define BATCH 4096
#define NUM_CLASSES 100000
#define FEAT_DIM 64
#define CLAMP_MIN_F 1e-12f
#define CLAMP_MAX_F 1e12f

#define BLOCK_THREADS 256
#define WARPS_PER_BLOCK 8
#define ROWS_PER_WARP 2
#define ROWS_PER_BLOCK (WARPS_PER_BLOCK * ROWS_PER_WARP)   // 16
#define NUM_BLOCKS (BATCH / ROWS_PER_BLOCK)                // 256

__device__ float g_partials[NUM_BLOCKS];

__global__ void __launch_bounds__(BLOCK_THREADS)
center_loss_rows(const float* __restrict__ x,
                 const float* __restrict__ centers,
                 const int* __restrict__ labels) {
    const int warp = threadIdx.x >> 5;
    const int lane = threadIdx.x & 31;
    const int row0 = blockIdx.x * ROWS_PER_BLOCK + warp * ROWS_PER_WARP;
    const int row1 = row0 + 1;

    int l0 = labels[row0];
    int l1 = labels[row1];
    // Crash guard (free): bad label -> wrong value, never a fault.
    l0 = (l0 < 0) ? 0 : (l0 >= NUM_CLASSES ? NUM_CLASSES - 1 : l0);
    l1 = (l1 < 0) ? 0 : (l1 >= NUM_CLASSES ? NUM_CLASSES - 1 : l1);

    // 4 independent 8B loads per lane -> MLP hides the label->center chain.
    const float2 xv0 = reinterpret_cast<const float2*>(x + (size_t)row0 * FEAT_DIM)[lane];
    const float2 xv1 = reinterpret_cast<const float2*>(x + (size_t)row1 * FEAT_DIM)[lane];
    const float2 cv0 = reinterpret_cast<const float2*>(centers + (size_t)l0 * FEAT_DIM)[lane];
    const float2 cv1 = reinterpret_cast<const float2*>(centers + (size_t)l1 * FEAT_DIM)[lane];

    const float e0 = xv0.x - cv0.x, e1 = xv0.y - cv0.y;
    const float f0 = xv1.x - cv1.x, f1 = xv1.y - cv1.y;
    float a0 = e0 * e0 + e1 * e1;
    float a1 = f0 * f0 + f1 * f1;

    #pragma unroll
    for (int o = 16; o > 0; o >>= 1) {
        a0 += __shfl_xor_sync(0xffffffffu, a0, o);
        a1 += __shfl_xor_sync(0xffffffffu, a1, o);
    }

    __shared__ float ws[WARPS_PER_BLOCK];
    if (lane == 0) {
        // clamp per ROW (clip-then-sum, faithful to reference)
        const float c0 = fminf(fmaxf(a0, CLAMP_MIN_F), CLAMP_MAX_F);
        const float c1 = fminf(fmaxf(a1, CLAMP_MIN_F), CLAMP_MAX_F);
        ws[warp] = c0 + c1;
    }
    __syncthreads();

    if (threadIdx.x == 0) {
        float v = 0.0f;
        #pragma unroll
        for (int w = 0; w < WARPS_PER_BLOCK; w++) v += ws[w];
        __stcg(&g_partials[blockIdx.x], v);   // publish via L2
    }
    // Let the dependent (PDL) grid launch as soon as this block is done.
    cudaTriggerProgrammaticLaunchCompletion();
}

__global__ void __launch_bounds__(NUM_BLOCKS)
center_loss_reduce(float* __restrict__ out) {
    // Launched programmatically while rows-grid is still running; this waits
    // for rows-grid completion and makes its global writes visible.
    cudaGridDependencySynchronize();

    const int tid = threadIdx.x;
    const int lane = tid & 31;
    const int wid = tid >> 5;

    float v = __ldcg(&g_partials[tid]);       // 256 slots, 256 threads, from L2

    #pragma unroll
    for (int o = 16; o > 0; o >>= 1)
        v += __shfl_xor_sync(0xffffffffu, v, o);

    __shared__ float ws[NUM_BLOCKS / 32];     // 8 warps
    if (lane == 0) ws[wid] = v;
    __syncthreads();

    if (tid == 0) {
        float w = 0.0f;
        #pragma unroll
        for (int i = 0; i < NUM_BLOCKS / 32; i++) w += ws[i];
        // (C-1) masked zeros per row -> CLAMP_MIN each; /B leaves (C-1)*MIN.
        const float mask_term = (float)(NUM_CLASSES - 1) * CLAMP_MIN_F;
        out[0] = w / (float)BATCH + mask_term;
    }
}

extern "C" void kernel_launch(void* const* d_in, const int* in_sizes, int n_in,
                              void* d_out, int out_size) {
    const float* x       = (const float*)d_in[0];
    const float* centers = (const float*)d_in[1];
    const int*   labels  = (const int*)d_in[2];
    float* out = (float*)d_out;

    center_loss_rows<<<NUM_BLOCKS, BLOCK_THREADS>>>(x, centers, labels);

    // Dependent launch: overlap this kernel's launch with rows execution.
    cudaLaunchConfig_t cfg = {};
    cfg.gridDim  = dim3(1, 1, 1);
    cfg.blockDim = dim3(NUM_BLOCKS, 1, 1);
    cfg.dynamicSmemBytes = 0;
    cfg.stream = 0;   // same (capture) stream as the <<<>>> launch above
    cudaLaunchAttribute attr[1];
    attr[0].id = cudaLaunchAttributeProgrammaticStreamSerialization;
    attr[0].val.programmaticStreamSerializationAllowed = 1;
    cfg.attrs = attr;
    cfg.numAttrs = 1;
    cudaLaunchKernelEx(&cfg, center_loss_reduce, out);
}

// round 9
// speedup vs baseline: 1.3125x; 1.0288x over previous
#include <cuda_runtime.h>
#include <cuda_bf16.h>

// CenterLoss collapses: the label mask keeps only distmat[b, labels[b]]; all
// other B*(C-1) entries are 0 -> clamped to CLAMP_MIN.
// loss = (sum_b clamp(||x_b - c_{lbl_b}||^2, MIN, MAX)) / B + (C-1)*CLAMP_MIN.
// Labels are INT32 (established R2..R5). PDL two-kernel skeleton (R8 win).
//
// R9: single-wave grid (128 blocks <= 148 SMs), 4 rows/warp (8 independent
// loads/lane -> 2x MLP), PDL trigger at kernel entry, smaller reduce tail.

#define BATCH 4096
#define NUM_CLASSES 100000
#define FEAT_DIM 64
#define CLAMP_MIN_F 1e-12f
#define CLAMP_MAX_F 1e12f

#define BLOCK_THREADS 256
#define WARPS_PER_BLOCK 8
#define ROWS_PER_WARP 4
#define ROWS_PER_BLOCK (WARPS_PER_BLOCK * ROWS_PER_WARP)   // 32
#define NUM_BLOCKS (BATCH / ROWS_PER_BLOCK)                // 128 -> single wave

__device__ float g_partials[NUM_BLOCKS];

__global__ void __launch_bounds__(BLOCK_THREADS)
center_loss_rows(const float* __restrict__ x,
                 const float* __restrict__ centers,
                 const int* __restrict__ labels) {
    // Allow the dependent reduce grid to launch immediately; its
    // cudaGridDependencySynchronize still waits for THIS grid's completion.
    cudaTriggerProgrammaticLaunchCompletion();

    const int warp = threadIdx.x >> 5;
    const int lane = threadIdx.x & 31;
    const int row0 = blockIdx.x * ROWS_PER_BLOCK + warp * ROWS_PER_WARP;

    int lb[ROWS_PER_WARP];
    #pragma unroll
    for (int r = 0; r < ROWS_PER_WARP; r++) {
        int l = labels[row0 + r];
        // Crash guard (free): bad label -> wrong value, never a fault.
        lb[r] = (l < 0) ? 0 : (l >= NUM_CLASSES ? NUM_CLASSES - 1 : l);
    }

    // 8 independent 8B loads per lane; fully coalesced 256B rows.
    float2 xv[ROWS_PER_WARP], cv[ROWS_PER_WARP];
    #pragma unroll
    for (int r = 0; r < ROWS_PER_WARP; r++)
        xv[r] = reinterpret_cast<const float2*>(x + (size_t)(row0 + r) * FEAT_DIM)[lane];
    #pragma unroll
    for (int r = 0; r < ROWS_PER_WARP; r++)
        cv[r] = reinterpret_cast<const float2*>(centers + (size_t)lb[r] * FEAT_DIM)[lane];

    float a[ROWS_PER_WARP];
    #pragma unroll
    for (int r = 0; r < ROWS_PER_WARP; r++) {
        const float d0 = xv[r].x - cv[r].x;
        const float d1 = xv[r].y - cv[r].y;
        a[r] = d0 * d0 + d1 * d1;
    }

    #pragma unroll
    for (int o = 16; o > 0; o >>= 1) {
        #pragma unroll
        for (int r = 0; r < ROWS_PER_WARP; r++)
            a[r] += __shfl_xor_sync(0xffffffffu, a[r], o);
    }

    __shared__ float ws[WARPS_PER_BLOCK];
    if (lane == 0) {
        // clamp per ROW (clip-then-sum, faithful to reference), fixed order
        float s = 0.0f;
        #pragma unroll
        for (int r = 0; r < ROWS_PER_WARP; r++)
            s += fminf(fmaxf(a[r], CLAMP_MIN_F), CLAMP_MAX_F);
        ws[warp] = s;
    }
    __syncthreads();

    if (threadIdx.x == 0) {
        float v = 0.0f;
        #pragma unroll
        for (int w = 0; w < WARPS_PER_BLOCK; w++) v += ws[w];
        __stcg(&g_partials[blockIdx.x], v);   // publish via L2
    }
}

__global__ void __launch_bounds__(NUM_BLOCKS)
center_loss_reduce(float* __restrict__ out) {
    // Launched programmatically while rows-grid runs; waits for its completion
    // and memory visibility.
    cudaGridDependencySynchronize();

    const int tid = threadIdx.x;     // 128 threads
    const int lane = tid & 31;
    const int wid = tid >> 5;

    float v = __ldcg(&g_partials[tid]);       // 128 slots, 128 threads, from L2

    #pragma unroll
    for (int o = 16; o > 0; o >>= 1)
        v += __shfl_xor_sync(0xffffffffu, v, o);

    __shared__ float ws[NUM_BLOCKS / 32];     // 4 warps
    if (lane == 0) ws[wid] = v;
    __syncthreads();

    if (tid == 0) {
        float w = 0.0f;
        #pragma unroll
        for (int i = 0; i < NUM_BLOCKS / 32; i++) w += ws[i];
        // (C-1) masked zeros per row -> CLAMP_MIN each; /B leaves (C-1)*MIN.
        const float mask_term = (float)(NUM_CLASSES - 1) * CLAMP_MIN_F;
        out[0] = w / (float)BATCH + mask_term;
    }
}

extern "C" void kernel_launch(void* const* d_in, const int* in_sizes, int n_in,
                              void* d_out, int out_size) {
    const float* x       = (const float*)d_in[0];
    const float* centers = (const float*)d_in[1];
    const int*   labels  = (const int*)d_in[2];
    float* out = (float*)d_out;

    center_loss_rows<<<NUM_BLOCKS, BLOCK_THREADS>>>(x, centers, labels);

    // Dependent launch: overlap this kernel's launch with rows execution.
    cudaLaunchConfig_t cfg = {};
    cfg.gridDim  = dim3(1, 1, 1);
    cfg.blockDim = dim3(NUM_BLOCKS, 1, 1);
    cfg.dynamicSmemBytes = 0;
    cfg.stream = 0;   // same (capture) stream as the <<<>>> launch above
    cudaLaunchAttribute attr[1];
    attr[0].id = cudaLaunchAttributeProgrammaticStreamSerialization;
    attr[0].val.programmaticStreamSerializationAllowed = 1;
    cfg.attrs = attr;
    cfg.numAttrs = 1;
    cudaLaunchKernelEx(&cfg, center_loss_reduce, out);
}

// round 10
// speedup vs baseline: 1.3858x; 1.0558x over previous
#include <cuda_runtime.h>
#include <cuda_bf16.h>

// CenterLoss collapses: the label mask keeps only distmat[b, labels[b]]; all
// other B*(C-1) entries are 0 -> clamped to CLAMP_MIN.
// loss = (sum_b clamp(||x_b - c_{lbl_b}||^2, MIN, MAX)) / B + (C-1)*CLAMP_MIN.
// Labels are INT32 (established R2..R5).
//
// R10: kill the reduce kernel. Node A = 1-thread init (out = mask_term).
// Node B = rows kernel (PDL-overlapped); each block leader RED-adds
// partial/BATCH to out. RED (atomic add, no return, single address) costs
// ~0.854 cyc/op vs the ~27 cyc/op serialized acq_rel ATOMGs that sank R7.

#define BATCH 4096
#define NUM_CLASSES 100000
#define FEAT_DIM 64
#define CLAMP_MIN_F 1e-12f
#define CLAMP_MAX_F 1e12f

#define BLOCK_THREADS 256
#define WARPS_PER_BLOCK 8
#define ROWS_PER_WARP 4
#define ROWS_PER_BLOCK (WARPS_PER_BLOCK * ROWS_PER_WARP)   // 32
#define NUM_BLOCKS (BATCH / ROWS_PER_BLOCK)                // 128 -> single wave

__global__ void __launch_bounds__(32)
center_loss_init(float* __restrict__ out) {
    // (C-1) masked zeros per row -> CLAMP_MIN each; /B leaves (C-1)*MIN.
    if (threadIdx.x == 0)
        out[0] = (float)(NUM_CLASSES - 1) * CLAMP_MIN_F;
}

__global__ void __launch_bounds__(BLOCK_THREADS)
center_loss_rows(const float* __restrict__ x,
                 const float* __restrict__ centers,
                 const int* __restrict__ labels,
                 float* __restrict__ out) {
    const int warp = threadIdx.x >> 5;
    const int lane = threadIdx.x & 31;
    const int row0 = blockIdx.x * ROWS_PER_BLOCK + warp * ROWS_PER_WARP;

    int lb[ROWS_PER_WARP];
    #pragma unroll
    for (int r = 0; r < ROWS_PER_WARP; r++) {
        int l = labels[row0 + r];
        // Crash guard (free): bad label -> wrong value, never a fault.
        lb[r] = (l < 0) ? 0 : (l >= NUM_CLASSES ? NUM_CLASSES - 1 : l);
    }

    // 8 independent 8B loads per lane; fully coalesced 256B rows.
    float2 xv[ROWS_PER_WARP], cv[ROWS_PER_WARP];
    #pragma unroll
    for (int r = 0; r < ROWS_PER_WARP; r++)
        xv[r] = reinterpret_cast<const float2*>(x + (size_t)(row0 + r) * FEAT_DIM)[lane];
    #pragma unroll
    for (int r = 0; r < ROWS_PER_WARP; r++)
        cv[r] = reinterpret_cast<const float2*>(centers + (size_t)lb[r] * FEAT_DIM)[lane];

    float a[ROWS_PER_WARP];
    #pragma unroll
    for (int r = 0; r < ROWS_PER_WARP; r++) {
        const float d0 = xv[r].x - cv[r].x;
        const float d1 = xv[r].y - cv[r].y;
        a[r] = d0 * d0 + d1 * d1;
    }

    #pragma unroll
    for (int o = 16; o > 0; o >>= 1) {
        #pragma unroll
        for (int r = 0; r < ROWS_PER_WARP; r++)
            a[r] += __shfl_xor_sync(0xffffffffu, a[r], o);
    }

    __shared__ float ws[WARPS_PER_BLOCK];
    if (lane == 0) {
        // clamp per ROW (clip-then-sum, faithful to reference), fixed order
        float s = 0.0f;
        #pragma unroll
        for (int r = 0; r < ROWS_PER_WARP; r++)
            s += fminf(fmaxf(a[r], CLAMP_MIN_F), CLAMP_MAX_F);
        ws[warp] = s;
    }
    __syncthreads();

    if (threadIdx.x == 0) {
        float v = 0.0f;
        #pragma unroll
        for (int w = 0; w < WARPS_PER_BLOCK; w++) v += ws[w];
        // Ensure the init kernel's out[0]=mask_term is complete & visible.
        cudaGridDependencySynchronize();
        // No-return atomic add -> RED. 128 single-address REDs ~ 110 cycles.
        atomicAdd(out, v * (1.0f / (float)BATCH));
    }
}

extern "C" void kernel_launch(void* const* d_in, const int* in_sizes, int n_in,
                              void* d_out, int out_size) {
    const float* x       = (const float*)d_in[0];
    const float* centers = (const float*)d_in[1];
    const int*   labels  = (const int*)d_in[2];
    float* out = (float*)d_out;

    center_loss_init<<<1, 32>>>(out);

    // PDL: rows launches while init is in flight; the grid-dependency sync
    // inside rows (before the REDs) provides the ordering.
    cudaLaunchConfig_t cfg = {};
    cfg.gridDim  = dim3(NUM_BLOCKS, 1, 1);
    cfg.blockDim = dim3(BLOCK_THREADS, 1, 1);
    cfg.dynamicSmemBytes = 0;
    cfg.stream = 0;   // same (capture) stream as the launch above
    cudaLaunchAttribute attr[1];
    attr[0].id = cudaLaunchAttributeProgrammaticStreamSerialization;
    attr[0].val.programmaticStreamSerializationAllowed = 1;
    cfg.attrs = attr;
    cfg.numAttrs = 1;
    cudaLaunchKernelEx(&cfg, center_loss_rows, x, centers, labels, out);
}